// round 4
// baseline (speedup 1.0000x reference)
#include <cuda_runtime.h>
#include <math.h>

#define NRR     4096
#define NLL     16384
#define KM      8
#define TK      10
#define CF      16
#define NBATCH  4
#define NBINS   4096
#define CAP     1024
#define F_LOG2PI 1.8378770664093453f

// ---------------- device scratch (no allocations allowed) ----------------
__device__ int    g_cnt[NBATCH];
__device__ int2   g_comp[NBATCH * NLL];   // (packed pos, lidar idx) per batch
__device__ int    g_fb[NBATCH * TK];      // lowest indices NOT in batch b (top_k -inf filler)
__device__ float4 g_part[NRR];            // per-radar: occ, matched, m*sum_logp, m*sum_int

__device__ __forceinline__ unsigned long long umin64(unsigned long long a, unsigned long long b) {
    return a < b ? a : b;
}
__device__ __forceinline__ float softplusf(float x) {
    return log1pf(expf(-fabsf(x))) + fmaxf(x, 0.0f);
}

// ---------------- setup kernels ----------------
__global__ void k_zero() {
    if (threadIdx.x < NBATCH) g_cnt[threadIdx.x] = 0;
}

__global__ void k_compact(const int* __restrict__ li) {
    int j = blockIdx.x * blockDim.x + threadIdx.x;
    if (j >= NLL) return;
    const int4 v = reinterpret_cast<const int4*>(li)[j];
    // cols: batch, c1<41, c2<176, c3<176  -> pack each into a byte
    int pack = (v.y << 16) | (v.z << 8) | v.w;
    int pos = atomicAdd(&g_cnt[v.x], 1);
    g_comp[v.x * NLL + pos] = make_int2(pack, j);
}

__global__ void k_fb(const int* __restrict__ li) {
    int b = threadIdx.x;
    if (b >= NBATCH) return;
    int c = 0;
    for (int j = 0; j < NLL && c < TK; ++j)
        if (li[j * 4] != b) g_fb[b * TK + c++] = j;
}

// ---------------- main per-radar kernel ----------------
__global__ __launch_bounds__(256) void k_main(
    const float* __restrict__ mu_off,  const float* __restrict__ log_sig_off,
    const float* __restrict__ mu_int,  const float* __restrict__ occ_logit,
    const float* __restrict__ mix_logit, const float* __restrict__ lfeat,
    const int* __restrict__ ridx, const int* __restrict__ lidx)
{
    __shared__ int s_hist[NBINS];
    __shared__ unsigned long long s_buf[CAP];
    __shared__ unsigned long long s_keys[TK];
    __shared__ int s_cnt2, s_thr;
    __shared__ float s_logpi[KM], s_muk[KM][3], s_invk[KM][3], s_ck[KM], s_mui[KM], s_occany;

    const int i   = blockIdx.x;
    const int tid = threadIdx.x;
    const int lane = tid & 31, wid = tid >> 5;

    const int4 r = reinterpret_cast<const int4*>(ridx)[i];
    const int rb = r.x, r1 = r.y, r2 = r.z, r3 = r.w;
    const int nb = g_cnt[rb];
    const int2* __restrict__ base = g_comp + rb * NLL;

    for (int q = tid; q < NBINS; q += 256) s_hist[q] = 0;
    if (tid == 0) s_cnt2 = 0;
    __syncthreads();

    // ---- pass 1: d^2 histogram over same-batch lidars ----
    for (int j = tid; j < nb; j += 256) {
        const int2 e = base[j];
        const int p = e.x;
        int d3 = (p & 255) - r3;
        int d2 = ((p >> 8) & 255) - r2;
        int d1 = (p >> 16) - r1;
        int dd = d1 * d1 + d2 * d2 + d3 * d3;
        atomicAdd(&s_hist[min(dd, NBINS - 1)], 1);
    }
    __syncthreads();

    // ---- find smallest d^2 threshold with cumulative count >= TK ----
    if (tid == 0) {
        int cum = 0, b = 0;
        for (; b < NBINS - 1; ++b) { cum += s_hist[b]; if (cum >= TK) break; }
        s_thr = b;   // if never reached: b == NBINS-1 -> collect everything
    }
    __syncthreads();
    const int thr = s_thr;

    // ---- pass 2: collect candidate keys (exact (d2, idx) ordering) ----
    for (int j = tid; j < nb; j += 256) {
        const int2 e = base[j];
        const int p = e.x;
        int d3 = (p & 255) - r3;
        int d2 = ((p >> 8) & 255) - r2;
        int d1 = (p >> 16) - r1;
        int dd = d1 * d1 + d2 * d2 + d3 * d3;
        if (min(dd, NBINS - 1) <= thr) {
            int pos = atomicAdd(&s_cnt2, 1);
            if (pos < CAP)
                s_buf[pos] = (((unsigned long long)(unsigned)dd) << 32) | (unsigned)e.y;
        }
    }
    __syncthreads();
    const int cnt2 = s_cnt2;

    if (cnt2 > CAP) {
        // pathological fallback: serial exact top-10 (never taken on real data)
        if (tid == 0) {
            unsigned long long best[TK];
            for (int t = 0; t < TK; ++t) best[t] = ~0ULL;
            for (int j = 0; j < nb; ++j) {
                const int2 e = base[j];
                const int p = e.x;
                int d3 = (p & 255) - r3;
                int d2 = ((p >> 8) & 255) - r2;
                int d1 = (p >> 16) - r1;
                int dd = d1 * d1 + d2 * d2 + d3 * d3;
                unsigned long long key = (((unsigned long long)(unsigned)dd) << 32) | (unsigned)e.y;
                if (key < best[TK - 1]) {
                    int t = TK - 1;
                    for (; t > 0 && best[t - 1] > key; --t) best[t] = best[t - 1];
                    best[t] = key;
                }
            }
            for (int t = 0; t < TK; ++t) s_keys[t] = best[t];
        }
    } else if (wid == 0) {
        // warp 0: extract 10 smallest unique keys from candidate buffer
        for (int t = 0; t < TK; ++t) {
            unsigned long long best = ~0ULL;
            for (int q = lane; q < cnt2; q += 32) best = umin64(best, s_buf[q]);
            #pragma unroll
            for (int d = 16; d; d >>= 1)
                best = umin64(best, __shfl_xor_sync(0xFFFFFFFFu, best, d));
            if (lane == 0) s_keys[t] = best;
            for (int q = lane; q < cnt2; q += 32)
                if (s_buf[q] == best) s_buf[q] = ~0ULL;
            __syncwarp();
        }
    }

    // warp 1: per-component precompute (log_softmax, sigma^-2, constants, occ max)
    if (wid == 1) {
        const int k = lane;
        float v = (k < KM) ? mix_logit[i * KM + k] : -INFINITY;
        float mx = v;
        #pragma unroll
        for (int d = 16; d; d >>= 1) mx = fmaxf(mx, __shfl_xor_sync(0xFFFFFFFFu, mx, d));
        float ex = (k < KM) ? expf(v - mx) : 0.0f;
        float sm = ex;
        #pragma unroll
        for (int d = 16; d; d >>= 1) sm += __shfl_xor_sync(0xFFFFFFFFu, sm, d);
        float lz = mx + logf(sm);

        float o = (k < KM) ? occ_logit[i * KM + k] : -INFINITY;
        float omx = o;
        #pragma unroll
        for (int d = 16; d; d >>= 1) omx = fmaxf(omx, __shfl_xor_sync(0xFFFFFFFFu, omx, d));
        if (lane == 0) s_occany = omx;

        if (k < KM) {
            s_logpi[k] = v - lz;
            const int bk = (i * KM + k) * 3;
            float l0 = log_sig_off[bk + 0], l1 = log_sig_off[bk + 1], l2 = log_sig_off[bk + 2];
            s_muk[k][0] = mu_off[bk + 0];
            s_muk[k][1] = mu_off[bk + 1];
            s_muk[k][2] = mu_off[bk + 2];
            s_invk[k][0] = 1.0f / (expf(2.0f * l0) + 1e-12f);
            s_invk[k][1] = 1.0f / (expf(2.0f * l1) + 1e-12f);
            s_invk[k][2] = 1.0f / (expf(2.0f * l2) + 1e-12f);
            s_ck[k]  = 2.0f * (l0 + l1 + l2) + 3.0f * F_LOG2PI;
            s_mui[k] = mu_int[i * KM + k];
        }
    }
    __syncthreads();

    // warp 0: per-slot MDN log-likelihood + intensity term, then reduce
    if (wid == 0) {
        const bool matched = nb > 0;
        float SL = 0.0f, SI = 0.0f;
        if (lane < TK) {
            int j;
            if (lane < nb) j = (int)(unsigned)(s_keys[lane] & 0xFFFFFFFFu);
            else           j = g_fb[rb * TK + (lane - nb)];   // reference's -inf tie filler
            const int4 lv = reinterpret_cast<const int4*>(lidx)[j];
            // y = offs_zyx reversed: (c3 diff, c2 diff, c1 diff); zeroed if unmatched
            float y0 = matched ? (float)(lv.w - r3) : 0.0f;
            float y1 = matched ? (float)(lv.z - r2) : 0.0f;
            float y2 = matched ? (float)(lv.y - r1) : 0.0f;
            const float* f = lfeat + j * CF;
            float gi = matched ? 0.25f * (f[3] + f[7] + f[11] + f[15]) : 0.0f;

            float lp[KM];
            float mx = -INFINITY;
            #pragma unroll
            for (int k = 0; k < KM; ++k) {
                float d0 = y0 - s_muk[k][0];
                float d1 = y1 - s_muk[k][1];
                float d2 = y2 - s_muk[k][2];
                float q = d0 * d0 * s_invk[k][0] + d1 * d1 * s_invk[k][1] + d2 * d2 * s_invk[k][2];
                lp[k] = -0.5f * (q + s_ck[k]) + s_logpi[k];
                mx = fmaxf(mx, lp[k]);
            }
            float se = 0.0f;
            #pragma unroll
            for (int k = 0; k < KM; ++k) se += expf(lp[k] - mx);
            float logp = mx + logf(se);
            SL = logp;
            float ai = 0.0f;
            #pragma unroll
            for (int k = 0; k < KM; ++k)
                ai += expf(lp[k] - logp) * fabsf(s_mui[k] - gi);
            SI = ai;
        }
        #pragma unroll
        for (int d = 16; d; d >>= 1) {
            SL += __shfl_xor_sync(0xFFFFFFFFu, SL, d);
            SI += __shfl_xor_sync(0xFFFFFFFFu, SI, d);
        }
        if (lane == 0) {
            float tgt = matched ? 1.0f : 0.0f;
            float occ = tgt * softplusf(-s_occany) + (1.0f - tgt) * softplusf(s_occany);
            g_part[i] = make_float4(occ, tgt, tgt * SL, tgt * SI);
        }
    }
}

// ---------------- deterministic final reduction ----------------
__global__ void k_reduce(float* __restrict__ out) {
    __shared__ double sh[256][4];
    const int tid = threadIdx.x;
    double a0 = 0, a1 = 0, a2 = 0, a3 = 0;
    for (int i = tid; i < NRR; i += 256) {
        float4 p = g_part[i];
        a0 += p.x; a1 += p.y; a2 += p.z; a3 += p.w;
    }
    sh[tid][0] = a0; sh[tid][1] = a1; sh[tid][2] = a2; sh[tid][3] = a3;
    __syncthreads();
    for (int s = 128; s; s >>= 1) {
        if (tid < s) {
            sh[tid][0] += sh[tid + s][0];
            sh[tid][1] += sh[tid + s][1];
            sh[tid][2] += sh[tid + s][2];
            sh[tid][3] += sh[tid + s][3];
        }
        __syncthreads();
    }
    if (tid == 0) {
        double occ_loss = sh[0][0] / (double)NRR;
        double cnt      = sh[0][1];
        double mdn_nll  = -sh[0][2] / (cnt * (double)TK);
        double int_loss =  sh[0][3] / (cnt * (double)TK * (double)KM);
        out[0] = (float)(0.2 * occ_loss + 1.0 * mdn_nll + 0.1 * int_loss);
    }
}

// ---------------- launch ----------------
extern "C" void kernel_launch(void* const* d_in, const int* in_sizes, int n_in,
                              void* d_out, int out_size) {
    const float* mu_off      = (const float*)d_in[0];
    const float* log_sig_off = (const float*)d_in[1];
    const float* mu_int      = (const float*)d_in[2];
    const float* occ_logit   = (const float*)d_in[3];
    const float* mix_logit   = (const float*)d_in[4];
    const float* lfeat       = (const float*)d_in[5];
    const int*   ridx        = (const int*)d_in[6];
    const int*   lidx        = (const int*)d_in[7];
    (void)in_sizes; (void)n_in; (void)out_size;   // gt_topk (d_in[8]) fixed at 10

    k_zero<<<1, 32>>>();
    k_compact<<<NLL / 256, 256>>>(lidx);
    k_fb<<<1, NBATCH>>>(lidx);
    k_main<<<NRR, 256>>>(mu_off, log_sig_off, mu_int, occ_logit, mix_logit,
                         lfeat, ridx, lidx);
    k_reduce<<<1, 256>>>((float*)d_out);
}

// round 5
// speedup vs baseline: 1.0066x; 1.0066x over previous
#include <cuda_runtime.h>
#include <math.h>

#define NRR   4096
#define NLL   16384
#define KM    8
#define TK    10
#define CF    16
#define NB    4
#define T2    400        // candidate d^2 threshold (10th-NN d^2 typ ~100, corners ~350)
#define CAPW  224        // per-warp candidate buffer
#define WPB   8          // warps (radars) per block
#define MAXB  (NRR/WPB + NB)
#define KNONE 0xFFFFFFFFu
#define F_LOG2PI 1.8378770664093453f

// ---------------- device scratch ----------------
__device__ int            g_lcnt[NB], g_rcnt[NB];
__device__ int            g_lpos[NB * NLL];     // packed (c1<<16)|(c2<<8)|c3 per batch
__device__ unsigned short g_lidx[NB * NLL];     // original lidar index
__device__ int            g_rord[NB * NRR];     // radar indices grouped by batch
__device__ int            g_fb[NB * TK];        // lowest indices NOT in batch b (-inf tie filler)
__device__ int            g_bstart[NB + 1];     // block-range prefix per batch
__device__ float4         g_part[NRR];          // occ, matched, m*sum_logp, m*sum_int
__device__ int            g_done;

__device__ __forceinline__ float softplusf(float x) {
    return log1pf(expf(-fabsf(x))) + fmaxf(x, 0.0f);
}

// ---------------- setup ----------------
__global__ void k_zero() {
    int t = threadIdx.x;
    if (t < NB) { g_lcnt[t] = 0; g_rcnt[t] = 0; }
    if (t == 0) g_done = 0;
}

__global__ void k_compact(const int* __restrict__ li, const int* __restrict__ ri) {
    int j = blockIdx.x * blockDim.x + threadIdx.x;
    const int4 v = reinterpret_cast<const int4*>(li)[j];
    int pos = atomicAdd(&g_lcnt[v.x], 1);
    g_lpos[v.x * NLL + pos] = (v.y << 16) | (v.z << 8) | v.w;
    g_lidx[v.x * NLL + pos] = (unsigned short)j;
    if (j < NRR) {
        const int4 rv = reinterpret_cast<const int4*>(ri)[j];
        int p2 = atomicAdd(&g_rcnt[rv.x], 1);
        g_rord[rv.x * NRR + p2] = j;
    }
}

__global__ void k_setup(const int* __restrict__ li) {
    int t = threadIdx.x;
    if (t < NB) {
        int c = 0;
        for (int j = 0; j < NLL && c < TK; ++j)
            if (li[j * 4] != t) g_fb[t * TK + c++] = j;
    }
    if (t == 0) {
        int s = 0;
        for (int b = 0; b < NB; ++b) { g_bstart[b] = s; s += (g_rcnt[b] + WPB - 1) / WPB; }
        g_bstart[NB] = s;
    }
}

// ---------------- main: one warp per radar ----------------
__global__ __launch_bounds__(256) void k_main(
    const float* __restrict__ mu_off,  const float* __restrict__ log_sig_off,
    const float* __restrict__ mu_int,  const float* __restrict__ occ_logit,
    const float* __restrict__ mix_logit, const float* __restrict__ lfeat,
    const int* __restrict__ ridx, const int* __restrict__ lidx,
    float* __restrict__ out)
{
    __shared__ unsigned s_buf[WPB][CAPW];
    __shared__ float    s_cmp[WPB][KM][9];  // logpi, mu0..2, inv0..2, ck, mui
    __shared__ double   s_red[256][4];
    __shared__ int      s_last;

    const int tid = threadIdx.x, lane = tid & 31, wid = tid >> 5;
    const int bid = blockIdx.x;
    const int total = g_bstart[NB];

    if (bid < total) {
        int b = 0;
        #pragma unroll
        for (int q = 1; q < NB; ++q) if (bid >= g_bstart[q]) b = q;
        const int ri_ = (bid - g_bstart[b]) * WPB + wid;
        if (ri_ < g_rcnt[b]) {
            const int i = g_rord[b * NRR + ri_];
            const int4 r = reinterpret_cast<const int4*>(ridx)[i];
            const int r1 = r.y, r2 = r.z, r3 = r.w;
            const int nbL = g_lcnt[b];
            const int* __restrict__ pp = g_lpos + b * NLL;
            const unsigned short* __restrict__ ii = g_lidx + b * NLL;

            // ---- single filtered pass: collect candidates with d^2 < T2 ----
            int cnt = 0;
            #pragma unroll 4
            for (int j0 = 0; j0 < nbL; j0 += 32) {
                int j = j0 + lane;
                bool pred = false; unsigned key = 0;
                if (j < nbL) {
                    int p = pp[j];
                    int d3 = (p & 255) - r3;
                    int d2 = ((p >> 8) & 255) - r2;
                    int d1 = (p >> 16) - r1;
                    int dd = d1 * d1 + d2 * d2 + d3 * d3;
                    if (dd < T2) { pred = true; key = ((unsigned)dd << 16) | ii[j]; }
                }
                unsigned m = __ballot_sync(0xFFFFFFFFu, pred);
                if (pred) {
                    int off = cnt + __popc(m & ((1u << lane) - 1u));
                    if (off < CAPW) s_buf[wid][off] = key;
                }
                cnt += __popc(m);
            }
            __syncwarp();

            // ---- exact top-10 extraction (keys ascending = (d2, idx) order) ----
            unsigned mykey = KNONE;
            const bool okp = (cnt <= CAPW) && (cnt >= TK || cnt == nbL);
            long long last = -1;
            if (okp) {
                #pragma unroll
                for (int t = 0; t < TK; ++t) {
                    unsigned best = KNONE;
                    for (int q = lane; q < cnt; q += 32) {
                        unsigned v = s_buf[wid][q];
                        if ((long long)v > last && v < best) best = v;
                    }
                    #pragma unroll
                    for (int d = 16; d; d >>= 1)
                        best = min(best, __shfl_xor_sync(0xFFFFFFFFu, best, d));
                    if (lane == t) mykey = best;
                    last = (long long)best;
                }
            } else {
                // guaranteed-correct fallback: extraction over all entries
                #pragma unroll 1
                for (int t = 0; t < TK; ++t) {
                    unsigned best = KNONE;
                    for (int q = lane; q < nbL; q += 32) {
                        int p = pp[q];
                        int d3 = (p & 255) - r3;
                        int d2 = ((p >> 8) & 255) - r2;
                        int d1 = (p >> 16) - r1;
                        int dd = d1 * d1 + d2 * d2 + d3 * d3;
                        unsigned v = ((unsigned)dd << 16) | ii[q];
                        if ((long long)v > last && v < best) best = v;
                    }
                    #pragma unroll
                    for (int d = 16; d; d >>= 1)
                        best = min(best, __shfl_xor_sync(0xFFFFFFFFu, best, d));
                    if (lane == t) mykey = best;
                    last = (long long)best;
                }
            }

            // ---- per-component precompute (lanes 0..7, warp-wide reductions) ----
            const int k = lane;
            float v = (k < KM) ? mix_logit[i * KM + k] : -INFINITY;
            float mx = v;
            #pragma unroll
            for (int d = 16; d; d >>= 1) mx = fmaxf(mx, __shfl_xor_sync(0xFFFFFFFFu, mx, d));
            float ex = (k < KM) ? expf(v - mx) : 0.0f;
            float sm = ex;
            #pragma unroll
            for (int d = 16; d; d >>= 1) sm += __shfl_xor_sync(0xFFFFFFFFu, sm, d);
            float lz = mx + logf(sm);

            float o = (k < KM) ? occ_logit[i * KM + k] : -INFINITY;
            #pragma unroll
            for (int d = 16; d; d >>= 1) o = fmaxf(o, __shfl_xor_sync(0xFFFFFFFFu, o, d));
            const float occ_any = o;

            if (k < KM) {
                const int bk = (i * KM + k) * 3;
                float l0 = log_sig_off[bk], l1 = log_sig_off[bk + 1], l2 = log_sig_off[bk + 2];
                s_cmp[wid][k][0] = v - lz;
                s_cmp[wid][k][1] = mu_off[bk];
                s_cmp[wid][k][2] = mu_off[bk + 1];
                s_cmp[wid][k][3] = mu_off[bk + 2];
                s_cmp[wid][k][4] = 1.0f / (expf(2.0f * l0) + 1e-12f);
                s_cmp[wid][k][5] = 1.0f / (expf(2.0f * l1) + 1e-12f);
                s_cmp[wid][k][6] = 1.0f / (expf(2.0f * l2) + 1e-12f);
                s_cmp[wid][k][7] = 2.0f * (l0 + l1 + l2) + 3.0f * F_LOG2PI;
                s_cmp[wid][k][8] = mu_int[i * KM + k];
            }
            __syncwarp();

            // ---- per-slot MDN log-likelihood + intensity (lanes 0..9) ----
            const bool matched = nbL > 0;
            const int nvalid = min(nbL, TK);
            float SL = 0.0f, SI = 0.0f;
            if (lane < TK) {
                int j = (mykey != KNONE) ? (int)(mykey & 0xFFFFu)
                                         : g_fb[b * TK + (lane - nvalid)];
                const int4 lv = reinterpret_cast<const int4*>(lidx)[j];
                float y0 = matched ? (float)(lv.w - r3) : 0.0f;
                float y1 = matched ? (float)(lv.z - r2) : 0.0f;
                float y2 = matched ? (float)(lv.y - r1) : 0.0f;
                const float* f = lfeat + j * CF;
                float gi = matched ? 0.25f * (f[3] + f[7] + f[11] + f[15]) : 0.0f;

                float lp[KM]; float pm = -INFINITY;
                #pragma unroll
                for (int kk = 0; kk < KM; ++kk) {
                    float d0 = y0 - s_cmp[wid][kk][1];
                    float d1 = y1 - s_cmp[wid][kk][2];
                    float d2 = y2 - s_cmp[wid][kk][3];
                    float qv = d0 * d0 * s_cmp[wid][kk][4] + d1 * d1 * s_cmp[wid][kk][5]
                             + d2 * d2 * s_cmp[wid][kk][6];
                    lp[kk] = -0.5f * (qv + s_cmp[wid][kk][7]) + s_cmp[wid][kk][0];
                    pm = fmaxf(pm, lp[kk]);
                }
                float se = 0.0f;
                #pragma unroll
                for (int kk = 0; kk < KM; ++kk) se += expf(lp[kk] - pm);
                float logp = pm + logf(se);
                SL = logp;
                float ai = 0.0f;
                #pragma unroll
                for (int kk = 0; kk < KM; ++kk)
                    ai += expf(lp[kk] - logp) * fabsf(s_cmp[wid][kk][8] - gi);
                SI = ai;
            }
            #pragma unroll
            for (int d = 16; d; d >>= 1) {
                SL += __shfl_xor_sync(0xFFFFFFFFu, SL, d);
                SI += __shfl_xor_sync(0xFFFFFFFFu, SI, d);
            }
            if (lane == 0) {
                float tgt = matched ? 1.0f : 0.0f;
                float occ = tgt * softplusf(-occ_any) + (1.0f - tgt) * softplusf(occ_any);
                g_part[i] = make_float4(occ, tgt, tgt * SL, tgt * SI);
            }
        }
    }

    // ---- last-block deterministic final reduction ----
    __threadfence();
    __syncthreads();
    if (tid == 0) s_last = (atomicAdd(&g_done, 1) == (int)gridDim.x - 1);
    __syncthreads();
    if (s_last) {
        double a0 = 0, a1 = 0, a2 = 0, a3 = 0;
        for (int q = tid; q < NRR; q += 256) {
            float4 p = g_part[q];
            a0 += p.x; a1 += p.y; a2 += p.z; a3 += p.w;
        }
        s_red[tid][0] = a0; s_red[tid][1] = a1; s_red[tid][2] = a2; s_red[tid][3] = a3;
        __syncthreads();
        for (int s = 128; s; s >>= 1) {
            if (tid < s) {
                s_red[tid][0] += s_red[tid + s][0];
                s_red[tid][1] += s_red[tid + s][1];
                s_red[tid][2] += s_red[tid + s][2];
                s_red[tid][3] += s_red[tid + s][3];
            }
            __syncthreads();
        }
        if (tid == 0) {
            double occ_loss = s_red[0][0] / (double)NRR;
            double cntm     = s_red[0][1];
            double mdn_nll  = -s_red[0][2] / (cntm * (double)TK);
            double int_loss =  s_red[0][3] / (cntm * (double)TK * (double)KM);
            out[0] = (float)(0.2 * occ_loss + 1.0 * mdn_nll + 0.1 * int_loss);
        }
    }
}

// ---------------- launch ----------------
extern "C" void kernel_launch(void* const* d_in, const int* in_sizes, int n_in,
                              void* d_out, int out_size) {
    const float* mu_off      = (const float*)d_in[0];
    const float* log_sig_off = (const float*)d_in[1];
    const float* mu_int      = (const float*)d_in[2];
    const float* occ_logit   = (const float*)d_in[3];
    const float* mix_logit   = (const float*)d_in[4];
    const float* lfeat       = (const float*)d_in[5];
    const int*   ridx        = (const int*)d_in[6];
    const int*   lidx        = (const int*)d_in[7];
    (void)in_sizes; (void)n_in; (void)out_size;

    k_zero<<<1, 32>>>();
    k_compact<<<NLL / 256, 256>>>(lidx, ridx);
    k_setup<<<1, 32>>>(lidx);
    k_main<<<MAXB, 256>>>(mu_off, log_sig_off, mu_int, occ_logit, mix_logit,
                          lfeat, ridx, lidx, (float*)d_out);
}

// round 6
// speedup vs baseline: 1.7895x; 1.7778x over previous
#include <cuda_runtime.h>
#include <math.h>
#include <limits.h>

#define NRR   4096
#define NLL   16384
#define KM    8
#define TK    10
#define CF    16
#define NB    4
#define CDX   3
#define CDY   11
#define CDZ   11
#define NCELL (CDX*CDY*CDZ)      // 363
#define NCB   (NB*NCELL)         // 1452
#define CAPW  512                // per-warp candidate buffer
#define WPB   8                  // radars per block (1 warp each)
#define KNONE 0xFFFFFFFFu
#define F_LOG2PI 1.8378770664093453f

// ---------------- device scratch ----------------
__device__ int            g_ccnt[NCB];
__device__ int            g_cstart[NCB + 1];
__device__ int            g_ccur[NCB];
__device__ int            g_cpos[NLL];       // packed (c1<<16)|(c2<<8)|c3, cell-sorted
__device__ unsigned short g_cidx[NLL];       // original lidar index, cell-sorted
__device__ int            g_fb[NB * TK];     // lowest indices NOT in batch b
__device__ float4         g_part[NRR];
__device__ int            g_done;

__device__ __forceinline__ float softplusf(float x) {
    return log1pf(expf(-fabsf(x))) + fmaxf(x, 0.0f);
}
__device__ __forceinline__ int cell_of(int b, int c1, int c2, int c3) {
    return b * NCELL + (((c1 >> 4) * CDY + (c2 >> 4)) * CDZ + (c3 >> 4));
}

// ---------------- setup ----------------
__global__ void k_zero(const int* __restrict__ li) {
    int t = blockIdx.x * blockDim.x + threadIdx.x;
    if (t < NCB) g_ccnt[t] = 0;
    if (t == NCB) g_done = 0;
    if (t >= NCB + 1 && t < NCB + 1 + NB) {     // g_fb for batch b
        int b = t - NCB - 1, c = 0;
        for (int j = 0; j < NLL && c < TK; ++j)
            if (li[j * 4] != b) g_fb[b * TK + c++] = j;
    }
}

__global__ void k_count(const int* __restrict__ li) {
    int j = blockIdx.x * blockDim.x + threadIdx.x;
    const int4 v = reinterpret_cast<const int4*>(li)[j];
    atomicAdd(&g_ccnt[cell_of(v.x, v.y, v.z, v.w)], 1);
}

__global__ void k_scan() {
    __shared__ int sh[512];
    const int t = threadIdx.x;
    const int base = t * 3;
    int c0 = (base     < NCB) ? g_ccnt[base]     : 0;
    int c1 = (base + 1 < NCB) ? g_ccnt[base + 1] : 0;
    int c2 = (base + 2 < NCB) ? g_ccnt[base + 2] : 0;
    int s = c0 + c1 + c2;
    sh[t] = s;
    __syncthreads();
    for (int d = 1; d < 512; d <<= 1) {
        int v = (t >= d) ? sh[t - d] : 0;
        __syncthreads();
        sh[t] += v;
        __syncthreads();
    }
    int e = sh[t] - s;
    if (base     < NCB) { g_cstart[base]     = e;           g_ccur[base]     = e; }
    if (base + 1 < NCB) { g_cstart[base + 1] = e + c0;      g_ccur[base + 1] = e + c0; }
    if (base + 2 < NCB) { g_cstart[base + 2] = e + c0 + c1; g_ccur[base + 2] = e + c0 + c1; }
    if (t == 511) g_cstart[NCB] = sh[511];
}

__global__ void k_scatter(const int* __restrict__ li) {
    int j = blockIdx.x * blockDim.x + threadIdx.x;
    const int4 v = reinterpret_cast<const int4*>(li)[j];
    int pos = atomicAdd(&g_ccur[cell_of(v.x, v.y, v.z, v.w)], 1);
    g_cpos[pos] = (v.y << 16) | (v.z << 8) | v.w;
    g_cidx[pos] = (unsigned short)j;
}

// ---------------- main: one warp per radar, grid-accelerated top-10 ----------------
__global__ __launch_bounds__(256) void k_main(
    const float* __restrict__ mu_off,  const float* __restrict__ log_sig_off,
    const float* __restrict__ mu_int,  const float* __restrict__ occ_logit,
    const float* __restrict__ mix_logit, const float* __restrict__ lfeat,
    const int* __restrict__ ridx, const int* __restrict__ lidx,
    float* __restrict__ out)
{
    __shared__ unsigned s_buf[WPB][CAPW];
    __shared__ float    s_cmp[WPB][KM][9];
    __shared__ double   s_red[256][4];
    __shared__ int      s_last;

    const int tid = threadIdx.x, lane = tid & 31, wid = tid >> 5;
    const int i = blockIdx.x * WPB + wid;

    {
        const int4 r = reinterpret_cast<const int4*>(ridx)[i];
        const int b = r.x, r1 = r.y, r2 = r.z, r3 = r.w;
        const int cx = r1 >> 4, cy = r2 >> 4, cz = r3 >> 4;
        const int bbeg = g_cstart[b * NCELL];
        const int bend = g_cstart[(b + 1) * NCELL];
        const int nbL  = bend - bbeg;

        int cnt = 0;
        #pragma unroll 1
        for (int R = 1;; ++R) {
            const int x0 = max(cx - R, 0), x1 = min(cx + R, CDX - 1);
            const int y0 = max(cy - R, 0), y1 = min(cy + R, CDY - 1);
            const int z0 = max(cz - R, 0), z1 = min(cz + R, CDZ - 1);
            int g = INT_MAX;
            if (x0 > 0)       g = min(g, r1 - x0 * 16);
            if (x1 < CDX - 1) g = min(g, (x1 + 1) * 16 - r1);
            if (y0 > 0)       g = min(g, r2 - y0 * 16);
            if (y1 < CDY - 1) g = min(g, (y1 + 1) * 16 - r2);
            if (z0 > 0)       g = min(g, r3 - z0 * 16);
            if (z1 < CDZ - 1) g = min(g, (z1 + 1) * 16 - r3);
            const unsigned g2 = (g == INT_MAX) ? 0x7FFFFFFFu : (unsigned)(g * g);
            const bool whole = (g == INT_MAX);

            cnt = 0;
            #pragma unroll 1
            for (int xx = x0; xx <= x1; ++xx) {
                #pragma unroll 1
                for (int yy = y0; yy <= y1; ++yy) {
                    const int crow = b * NCELL + ((xx * CDY + yy) * CDZ);
                    const int beg = g_cstart[crow + z0];
                    const int end = g_cstart[crow + z1 + 1];
                    for (int j0 = beg; j0 < end; j0 += 32) {
                        const int j = j0 + lane;
                        bool pred = false; unsigned key = 0;
                        if (j < end) {
                            const int p = g_cpos[j];
                            int d3 = (p & 255) - r3;
                            int d2 = ((p >> 8) & 255) - r2;
                            int d1 = (p >> 16) - r1;
                            unsigned dd = (unsigned)(d1 * d1 + d2 * d2 + d3 * d3);
                            if (dd < g2) { pred = true; key = (dd << 16) | g_cidx[j]; }
                        }
                        unsigned m = __ballot_sync(0xFFFFFFFFu, pred);
                        if (pred) {
                            int off = cnt + __popc(m & ((1u << lane) - 1u));
                            if (off < CAPW) s_buf[wid][off] = key;
                        }
                        cnt += __popc(m);
                    }
                }
            }
            if (cnt >= TK || whole) break;
        }

        // ---- exact top-10 extraction ----
        unsigned mykey = KNONE;
        long long last = -1;
        if (cnt <= CAPW) {
            #pragma unroll
            for (int t = 0; t < TK; ++t) {
                unsigned best = KNONE;
                for (int q = lane; q < cnt; q += 32) {
                    unsigned v = s_buf[wid][q];
                    if ((long long)v > last && v < best) best = v;
                }
                #pragma unroll
                for (int d = 16; d; d >>= 1)
                    best = min(best, __shfl_xor_sync(0xFFFFFFFFu, best, d));
                if (lane == t) mykey = best;
                last = (long long)best;
            }
        } else {
            // overflow fallback: exact extraction over whole batch (never on real data)
            #pragma unroll 1
            for (int t = 0; t < TK; ++t) {
                unsigned best = KNONE;
                for (int q = bbeg + lane; q < bend; q += 32) {
                    const int p = g_cpos[q];
                    int d3 = (p & 255) - r3;
                    int d2 = ((p >> 8) & 255) - r2;
                    int d1 = (p >> 16) - r1;
                    unsigned dd = (unsigned)(d1 * d1 + d2 * d2 + d3 * d3);
                    unsigned v = (dd << 16) | g_cidx[q];
                    if ((long long)v > last && v < best) best = v;
                }
                #pragma unroll
                for (int d = 16; d; d >>= 1)
                    best = min(best, __shfl_xor_sync(0xFFFFFFFFu, best, d));
                if (lane == t) mykey = best;
                last = (long long)best;
            }
        }

        // ---- per-component precompute (lanes 0..7) ----
        const int k = lane;
        float v = (k < KM) ? mix_logit[i * KM + k] : -INFINITY;
        float mx = v;
        #pragma unroll
        for (int d = 16; d; d >>= 1) mx = fmaxf(mx, __shfl_xor_sync(0xFFFFFFFFu, mx, d));
        float ex = (k < KM) ? expf(v - mx) : 0.0f;
        float sm = ex;
        #pragma unroll
        for (int d = 16; d; d >>= 1) sm += __shfl_xor_sync(0xFFFFFFFFu, sm, d);
        float lz = mx + logf(sm);

        float o = (k < KM) ? occ_logit[i * KM + k] : -INFINITY;
        #pragma unroll
        for (int d = 16; d; d >>= 1) o = fmaxf(o, __shfl_xor_sync(0xFFFFFFFFu, o, d));
        const float occ_any = o;

        if (k < KM) {
            const int bk = (i * KM + k) * 3;
            float l0 = log_sig_off[bk], l1 = log_sig_off[bk + 1], l2 = log_sig_off[bk + 2];
            s_cmp[wid][k][0] = v - lz;
            s_cmp[wid][k][1] = mu_off[bk];
            s_cmp[wid][k][2] = mu_off[bk + 1];
            s_cmp[wid][k][3] = mu_off[bk + 2];
            s_cmp[wid][k][4] = 1.0f / (expf(2.0f * l0) + 1e-12f);
            s_cmp[wid][k][5] = 1.0f / (expf(2.0f * l1) + 1e-12f);
            s_cmp[wid][k][6] = 1.0f / (expf(2.0f * l2) + 1e-12f);
            s_cmp[wid][k][7] = 2.0f * (l0 + l1 + l2) + 3.0f * F_LOG2PI;
            s_cmp[wid][k][8] = mu_int[i * KM + k];
        }
        __syncwarp();

        // ---- per-slot MDN + intensity (lanes 0..9) ----
        const bool matched = nbL > 0;
        unsigned rm = __ballot_sync(0xFFFFFFFFu, mykey != KNONE && lane < TK);
        const int nvalid = __popc(rm);
        float SL = 0.0f, SI = 0.0f;
        if (lane < TK) {
            int j = (mykey != KNONE) ? (int)(mykey & 0xFFFFu)
                                     : g_fb[b * TK + (lane - nvalid)];
            const int4 lv = reinterpret_cast<const int4*>(lidx)[j];
            float y0 = matched ? (float)(lv.w - r3) : 0.0f;
            float y1 = matched ? (float)(lv.z - r2) : 0.0f;
            float y2 = matched ? (float)(lv.y - r1) : 0.0f;
            const float* f = lfeat + j * CF;
            float gi = matched ? 0.25f * (f[3] + f[7] + f[11] + f[15]) : 0.0f;

            float lp[KM]; float pm = -INFINITY;
            #pragma unroll
            for (int kk = 0; kk < KM; ++kk) {
                float d0 = y0 - s_cmp[wid][kk][1];
                float d1 = y1 - s_cmp[wid][kk][2];
                float d2 = y2 - s_cmp[wid][kk][3];
                float qv = d0 * d0 * s_cmp[wid][kk][4] + d1 * d1 * s_cmp[wid][kk][5]
                         + d2 * d2 * s_cmp[wid][kk][6];
                lp[kk] = -0.5f * (qv + s_cmp[wid][kk][7]) + s_cmp[wid][kk][0];
                pm = fmaxf(pm, lp[kk]);
            }
            float se = 0.0f;
            #pragma unroll
            for (int kk = 0; kk < KM; ++kk) se += expf(lp[kk] - pm);
            float logp = pm + logf(se);
            SL = logp;
            float ai = 0.0f;
            #pragma unroll
            for (int kk = 0; kk < KM; ++kk)
                ai += expf(lp[kk] - logp) * fabsf(s_cmp[wid][kk][8] - gi);
            SI = ai;
        }
        #pragma unroll
        for (int d = 16; d; d >>= 1) {
            SL += __shfl_xor_sync(0xFFFFFFFFu, SL, d);
            SI += __shfl_xor_sync(0xFFFFFFFFu, SI, d);
        }
        if (lane == 0) {
            float tgt = matched ? 1.0f : 0.0f;
            float occ = tgt * softplusf(-occ_any) + (1.0f - tgt) * softplusf(occ_any);
            g_part[i] = make_float4(occ, tgt, tgt * SL, tgt * SI);
        }
    }

    // ---- last-block deterministic final reduction ----
    __threadfence();
    __syncthreads();
    if (tid == 0) s_last = (atomicAdd(&g_done, 1) == (int)gridDim.x - 1);
    __syncthreads();
    if (s_last) {
        double a0 = 0, a1 = 0, a2 = 0, a3 = 0;
        for (int q = tid; q < NRR; q += 256) {
            float4 p = g_part[q];
            a0 += p.x; a1 += p.y; a2 += p.z; a3 += p.w;
        }
        s_red[tid][0] = a0; s_red[tid][1] = a1; s_red[tid][2] = a2; s_red[tid][3] = a3;
        __syncthreads();
        for (int s = 128; s; s >>= 1) {
            if (tid < s) {
                s_red[tid][0] += s_red[tid + s][0];
                s_red[tid][1] += s_red[tid + s][1];
                s_red[tid][2] += s_red[tid + s][2];
                s_red[tid][3] += s_red[tid + s][3];
            }
            __syncthreads();
        }
        if (tid == 0) {
            double occ_loss = s_red[0][0] / (double)NRR;
            double cntm     = s_red[0][1];
            double mdn_nll  = -s_red[0][2] / (cntm * (double)TK);
            double int_loss =  s_red[0][3] / (cntm * (double)TK * (double)KM);
            out[0] = (float)(0.2 * occ_loss + 1.0 * mdn_nll + 0.1 * int_loss);
        }
    }
}

// ---------------- launch ----------------
extern "C" void kernel_launch(void* const* d_in, const int* in_sizes, int n_in,
                              void* d_out, int out_size) {
    const float* mu_off      = (const float*)d_in[0];
    const float* log_sig_off = (const float*)d_in[1];
    const float* mu_int      = (const float*)d_in[2];
    const float* occ_logit   = (const float*)d_in[3];
    const float* mix_logit   = (const float*)d_in[4];
    const float* lfeat       = (const float*)d_in[5];
    const int*   ridx        = (const int*)d_in[6];
    const int*   lidx        = (const int*)d_in[7];
    (void)in_sizes; (void)n_in; (void)out_size;

    k_zero<<<(NCB + 1 + NB + 255) / 256, 256>>>(lidx);
    k_count<<<NLL / 256, 256>>>(lidx);
    k_scan<<<1, 512>>>();
    k_scatter<<<NLL / 256, 256>>>(lidx);
    k_main<<<NRR / WPB, 256>>>(mu_off, log_sig_off, mu_int, occ_logit, mix_logit,
                               lfeat, ridx, lidx, (float*)d_out);
}